// round 12
// baseline (speedup 1.0000x reference)
#include <cuda_runtime.h>
#include <cstdint>

typedef unsigned int u32;

#define NPG   64
#define IN_F  128
#define OUT_F 128
#define XS_STRIDE 132     // X words/row: A-LDS banks 4*gid+tig -> conflict-free
#define WS_STRIDE 136     // W words/row: B-LDS banks 8*tig+gid -> conflict-free
#define KCHUNK 32
#define NBUF 3

#define XS_WORDS (NPG * XS_STRIDE)          // 8448
#define WBUF_WORDS (KCHUNK * WS_STRIDE)     // 4352
#define SMEM_BYTES ((XS_WORDS + NBUF * WBUF_WORDS) * 4)   // 86016

#define CVT_TF32(d, s) asm("cvt.rna.tf32.f32 %0, %1;" : "=r"(d) : "f"(s))
#define CP_ASYNC16(dst, src) \
    asm volatile("cp.async.cg.shared.global [%0], [%1], 16;" :: "r"(dst), "l"(src))
#define CP_COMMIT() asm volatile("cp.async.commit_group;" ::: "memory")
#define CP_WAIT(n)  asm volatile("cp.async.wait_group %0;" :: "n"(n) : "memory")

__device__ __forceinline__ u32 smem_addr(const void* p) {
    return (u32)__cvta_generic_to_shared(p);
}

__device__ __forceinline__ void mma_tf32(float* c,
                                         u32 a0, u32 a1, u32 a2, u32 a3,
                                         u32 b0, u32 b1)
{
    asm volatile(
        "mma.sync.aligned.m16n8k8.row.col.f32.tf32.tf32.f32 "
        "{%0,%1,%2,%3}, {%4,%5,%6,%7}, {%8,%9}, {%0,%1,%2,%3};"
        : "+f"(c[0]), "+f"(c[1]), "+f"(c[2]), "+f"(c[3])
        : "r"(a0), "r"(a1), "r"(a2), "r"(a3), "r"(b0), "r"(b1));
}

__global__ void __launch_bounds__(256, 2)
mhl_mma_kernel(const float* __restrict__ x,
               const int*   __restrict__ head,
               const float* __restrict__ kern,
               const float* __restrict__ bias,
               float*       __restrict__ out)
{
    extern __shared__ u32 smem[];
    u32* Xs = smem;                      // tf32 X[node][k], stride 132
    u32* Wb = smem + XS_WORDS;           // 3 ring buffers of W fp32 chunks [32 k][stride 136]

    const int tid  = threadIdx.x;
    const int wid  = tid >> 5;           // 8 warps: 2m x 4n
    const int lane = tid & 31;
    const int gid  = lane >> 2;
    const int tig  = lane & 3;
    const int g    = blockIdx.x;
    const int h    = __ldg(head + g);

    const int m0 = (wid >> 2) * 32;      // 0, 32
    const int n0 = (wid & 3) * 32;       // 0,32,64,96

    const float* W = kern + (size_t)h * IN_F * OUT_F;

    // per-thread cp.async coords for a W chunk: 1024 segs of 16B, 4 per thread
    // seg idx = tid + i*256 -> row r = idx>>5 (0..31), seg = idx&31
    // issue chunk c into buffer b
    auto issue_w = [&](int c, int b) {
        const float* src_base = W + (size_t)c * KCHUNK * OUT_F;
        u32 dst_base = smem_addr(Wb + b * WBUF_WORDS);
        #pragma unroll
        for (int i = 0; i < 4; i++) {
            const int idx = tid + i * 256;
            const int r   = idx >> 5;
            const int sg  = idx & 31;
            CP_ASYNC16(dst_base + (u32)(r * WS_STRIDE + sg * 4) * 4u,
                       src_base + r * OUT_F + sg * 4);
        }
        CP_COMMIT();
    };

    // prologue: 3 chunks in flight
    issue_w(0, 0);
    issue_w(1, 1);
    issue_w(2, 2);

    // ---- stage X[g] -> smem tf32 (overlaps with W cp.asyncs) ----
    {
        const float4* X4 = (const float4*)(x + (size_t)g * NPG * IN_F);
        #pragma unroll
        for (int it = 0; it < 8; it++) {
            const int idx  = tid + it * 256;      // 2048 float4
            const int node = idx >> 5;
            const int c4   = idx & 31;
            float4 v = X4[idx];
            u32 r0, r1, r2, r3;
            CVT_TF32(r0, v.x); CVT_TF32(r1, v.y);
            CVT_TF32(r2, v.z); CVT_TF32(r3, v.w);
            u32* dst = &Xs[node * XS_STRIDE + c4 * 4];
            dst[0] = r0; dst[1] = r1; dst[2] = r2; dst[3] = r3;
        }
    }

    float acc[2][4][4];
    #pragma unroll
    for (int i = 0; i < 2; i++)
        #pragma unroll
        for (int j = 0; j < 4; j++)
            #pragma unroll
            for (int r = 0; r < 4; r++)
                acc[i][j][r] = 0.0f;

    const u32* pX = Xs + (m0 + gid) * XS_STRIDE + tig;

    // compute one 32-k chunk from buffer b (k base = 32*c)
    auto compute_chunk = [&](int c, int b) {
        const u32* Wc = Wb + b * WBUF_WORDS;
        const u32* pB = Wc + tig * WS_STRIDE + n0 + gid;
        #pragma unroll
        for (int s = 0; s < 4; s++) {
            u32 b0[4], b1[4];
            const u32* pb = pB + s * 8 * WS_STRIDE;
            #pragma unroll
            for (int j = 0; j < 4; j++) {
                b0[j] = pb[j * 8];
                b1[j] = pb[4 * WS_STRIDE + j * 8];
            }
            #pragma unroll
            for (int i = 0; i < 2; i++) {
                const u32* pa = pX + i * 16 * XS_STRIDE + c * KCHUNK + s * 8;
                u32 a0 = pa[0];
                u32 a1 = pa[8 * XS_STRIDE];
                u32 a2 = pa[4];
                u32 a3 = pa[8 * XS_STRIDE + 4];
                #pragma unroll
                for (int j = 0; j < 4; j++)
                    mma_tf32(acc[i][j], a0, a1, a2, a3, b0[j], b1[j]);
            }
        }
    };

    // pipelined chunks: wait -> sync -> compute -> sync -> refill
    CP_WAIT(2); __syncthreads();
    compute_chunk(0, 0);
    __syncthreads();                      // all warps done with buf 0
    issue_w(3, 0);

    CP_WAIT(2); __syncthreads();
    compute_chunk(1, 1);

    CP_WAIT(1); __syncthreads();
    compute_chunk(2, 2);

    CP_WAIT(0); __syncthreads();
    compute_chunk(3, 0);

    // ---- epilogue: bias + coalesced float2 stores ----
    float bb[4][2];
    #pragma unroll
    for (int j = 0; j < 4; j++) {
        const int col = n0 + 8 * j + 2 * tig;
        bb[j][0] = __ldg(bias + (size_t)h * OUT_F + col);
        bb[j][1] = __ldg(bias + (size_t)h * OUT_F + col + 1);
    }

    #pragma unroll
    for (int i = 0; i < 2; i++) {
        const int node0 = g * NPG + m0 + 16 * i + gid;
        #pragma unroll
        for (int j = 0; j < 4; j++) {
            const int col = n0 + 8 * j + 2 * tig;
            float2 v0 = make_float2(acc[i][j][0] + bb[j][0], acc[i][j][1] + bb[j][1]);
            float2 v1 = make_float2(acc[i][j][2] + bb[j][0], acc[i][j][3] + bb[j][1]);
            *(float2*)&out[(size_t)node0 * OUT_F + col]       = v0;
            *(float2*)&out[(size_t)(node0 + 8) * OUT_F + col] = v1;
        }
    }
}

extern "C" void kernel_launch(void* const* d_in, const int* in_sizes, int n_in,
                              void* d_out, int out_size)
{
    const float* inputs = (const float*)d_in[0];
    const int*   head   = (const int*)d_in[2];
    const float* kern   = (const float*)d_in[3];
    const float* bias   = (const float*)d_in[4];
    float*       out    = (float*)d_out;
    const int n_graphs  = in_sizes[2];   // 256

    static bool attr_set = false;
    if (!attr_set) {
        cudaFuncSetAttribute(mhl_mma_kernel, cudaFuncAttributeMaxDynamicSharedMemorySize, SMEM_BYTES);
        attr_set = true;
    }
    mhl_mma_kernel<<<n_graphs, 256, SMEM_BYTES>>>(inputs, head, kern, bias, out);
}

// round 13
// speedup vs baseline: 1.0029x; 1.0029x over previous
#include <cuda_runtime.h>
#include <cuda_fp16.h>
#include <cstdint>

typedef unsigned int u32;

#define NPG   64
#define IN_F  128
#define OUT_F 128
#define N_CTA 64    // output columns per CTA
#define XS2   68    // X row stride (half2 words): A banks gid*4+tig -> conflict-free
#define WS2   72    // W pair-row stride (half2 words): 72%32==8 -> B banks tig*8+gid -> conflict-free

__device__ __forceinline__ u32 pack_h2(float lo, float hi) {
    __half2 h = __floats2half2_rn(lo, hi);
    return *(u32*)&h;
}

__device__ __forceinline__ void mma_f16(float* c, u32 a0, u32 a1, u32 a2, u32 a3,
                                        u32 b0, u32 b1)
{
    asm volatile(
        "mma.sync.aligned.m16n8k16.row.col.f32.f16.f16.f32 "
        "{%0,%1,%2,%3}, {%4,%5,%6,%7}, {%8,%9}, {%0,%1,%2,%3};"
        : "+f"(c[0]), "+f"(c[1]), "+f"(c[2]), "+f"(c[3])
        : "r"(a0), "r"(a1), "r"(a2), "r"(a3), "r"(b0), "r"(b1));
}

#define WP_WORDS (64 * WS2)                      // 4608 u32
#define XP_WORDS (NPG * XS2)                     // 4352 u32
#define SMEM_BYTES ((WP_WORDS + XP_WORDS) * 4)   // 35840 B

__global__ void __launch_bounds__(256)
mhl_mma_kernel(const float* __restrict__ x,
               const int*   __restrict__ head,
               const float* __restrict__ kern,
               const float* __restrict__ bias,
               float*       __restrict__ out)
{
    extern __shared__ u32 smem[];
    u32* Wp = smem;               // half2 W k-pairs: row r -> (W[2r][n], W[2r+1][n]), n in CTA slice
    u32* Xp = smem + WP_WORDS;    // half2 X k-pairs: Xp[node][kp]

    const int tid  = threadIdx.x;
    const int wid  = tid >> 5;            // 8 warps: 2m x 4n
    const int lane = tid & 31;
    const int gid  = lane >> 2;
    const int tig  = lane & 3;
    const int g    = blockIdx.x >> 1;     // graph
    const int nh   = blockIdx.x & 1;      // n-half
    const int n0c  = nh * N_CTA;          // CTA column base
    const int h    = __ldg(head + g);

    const int m0  = (wid >> 2) * 32;      // 0, 32
    const int n0w = (wid & 3) * 16;       // 0,16,32,48 within CTA slice

    // ---- stage W[h][:, n0c:n0c+64] -> Wp fp16 k-pairs ----
    {
        const float* W = kern + (size_t)h * IN_F * OUT_F + n0c;
        #pragma unroll
        for (int it = 0; it < 4; it++) {
            const int idx = tid + it * 256;       // 1024 tasks: 64 pair-rows x 16 float4
            const int r   = idx >> 4;             // k-pair row
            const int c4  = idx & 15;             // float4 within n-slice
            const float4* s0 = (const float4*)(W + (size_t)(2 * r)     * OUT_F) + c4;
            const float4* s1 = (const float4*)(W + (size_t)(2 * r + 1) * OUT_F) + c4;
            float4 va = *s0, vb = *s1;
            uint4 o;
            o.x = pack_h2(va.x, vb.x);
            o.y = pack_h2(va.y, vb.y);
            o.z = pack_h2(va.z, vb.z);
            o.w = pack_h2(va.w, vb.w);
            *(uint4*)&Wp[r * WS2 + c4 * 4] = o;
        }
    }
    // ---- stage X[g] -> Xp fp16 k-pairs ----
    {
        const float4* X4 = (const float4*)(x + (size_t)g * NPG * IN_F);
        #pragma unroll
        for (int it = 0; it < 8; it++) {
            const int idx  = tid + it * 256;      // 2048 float4
            const int node = idx >> 5;
            const int c4   = idx & 31;
            float4 v = X4[idx];
            uint2 o;
            o.x = pack_h2(v.x, v.y);
            o.y = pack_h2(v.z, v.w);
            *(uint2*)&Xp[node * XS2 + c4 * 2] = o;
        }
    }
    __syncthreads();

    float acc[2][2][4];
    #pragma unroll
    for (int i = 0; i < 2; i++)
        #pragma unroll
        for (int j = 0; j < 2; j++)
            #pragma unroll
            for (int r = 0; r < 4; r++)
                acc[i][j][r] = 0.0f;

    const u32* pA = Xp + (m0 + gid) * XS2 + tig;
    const u32* pB = Wp + tig * WS2 + n0w + gid;

    #pragma unroll
    for (int s = 0; s < 8; s++) {
        // B fragments: 2 n-tiles
        const u32* pb = pB + s * 8 * WS2;
        u32 b0[2], b1[2];
        #pragma unroll
        for (int j = 0; j < 2; j++) {
            b0[j] = pb[8 * j];
            b1[j] = pb[4 * WS2 + 8 * j];
        }
        // A fragments: 2 m-tiles, 4 MMAs
        #pragma unroll
        for (int i = 0; i < 2; i++) {
            const u32* pa = pA + i * 16 * XS2 + s * 8;
            u32 a0 = pa[0];
            u32 a1 = pa[8 * XS2];
            u32 a2 = pa[4];
            u32 a3 = pa[8 * XS2 + 4];
            mma_f16(acc[i][0], a0, a1, a2, a3, b0[0], b1[0]);
            mma_f16(acc[i][1], a0, a1, a2, a3, b0[1], b1[1]);
        }
    }

    // ---- epilogue: bias + coalesced float2 stores ----
    float bb[2][2];
    #pragma unroll
    for (int j = 0; j < 2; j++) {
        const int col = n0c + n0w + 8 * j + 2 * tig;
        bb[j][0] = __ldg(bias + (size_t)h * OUT_F + col);
        bb[j][1] = __ldg(bias + (size_t)h * OUT_F + col + 1);
    }

    #pragma unroll
    for (int i = 0; i < 2; i++) {
        const int node0 = g * NPG + m0 + 16 * i + gid;
        #pragma unroll
        for (int j = 0; j < 2; j++) {
            const int col = n0c + n0w + 8 * j + 2 * tig;
            float2 v0 = make_float2(acc[i][j][0] + bb[j][0], acc[i][j][1] + bb[j][1]);
            float2 v1 = make_float2(acc[i][j][2] + bb[j][0], acc[i][j][3] + bb[j][1]);
            *(float2*)&out[(size_t)node0 * OUT_F + col]       = v0;
            *(float2*)&out[(size_t)(node0 + 8) * OUT_F + col] = v1;
        }
    }
}

extern "C" void kernel_launch(void* const* d_in, const int* in_sizes, int n_in,
                              void* d_out, int out_size)
{
    const float* inputs = (const float*)d_in[0];
    const int*   head   = (const int*)d_in[2];
    const float* kern   = (const float*)d_in[3];
    const float* bias   = (const float*)d_in[4];
    float*       out    = (float*)d_out;
    const int n_graphs  = in_sizes[2];   // 256

    static bool attr_set = false;
    if (!attr_set) {
        cudaFuncSetAttribute(mhl_mma_kernel, cudaFuncAttributeMaxDynamicSharedMemorySize, SMEM_BYTES);
        attr_set = true;
    }
    mhl_mma_kernel<<<n_graphs * 2, 256, SMEM_BYTES>>>(inputs, head, kern, bias, out);
}

// round 14
// speedup vs baseline: 1.0239x; 1.0209x over previous
#include <cuda_runtime.h>
#include <cuda_fp16.h>
#include <cstdint>

typedef unsigned int u32;

#define NPG   64
#define IN_F  128
#define OUT_F 128
#define XI_STRIDE 72    // u32/row; 72%32==8 -> A LDS.64 banks 8*gid+2*tig, conflict-free/phase
#define WI_STRIDE 264   // u32/row; 264%32==8 -> B LDS.64 banks 8*tig+2*gid, conflict-free/phase

#define WI_WORDS (32 * WI_STRIDE)   // 8448
#define XI_WORDS (64 * XI_STRIDE)   // 4608
#define SMEM_BYTES ((WI_WORDS + XI_WORDS) * 4)   // 52224

__device__ __forceinline__ u32 pack_h2(float lo, float hi) {
    __half2 h = __floats2half2_rn(lo, hi);
    return *(u32*)&h;
}

__device__ __forceinline__ void mma_f16(float* c, u32 a0, u32 a1, u32 a2, u32 a3,
                                        u32 b0, u32 b1)
{
    asm volatile(
        "mma.sync.aligned.m16n8k16.row.col.f32.f16.f16.f32 "
        "{%0,%1,%2,%3}, {%4,%5,%6,%7}, {%8,%9}, {%0,%1,%2,%3};"
        : "+f"(c[0]), "+f"(c[1]), "+f"(c[2]), "+f"(c[3])
        : "r"(a0), "r"(a1), "r"(a2), "r"(a3), "r"(b0), "r"(b1));
}

__global__ void __launch_bounds__(512, 2)
mhl_mma_kernel(const float* __restrict__ x,
               const int*   __restrict__ head,
               const float* __restrict__ kern,
               const float* __restrict__ bias,
               float*       __restrict__ out)
{
    extern __shared__ u32 smem[];
    u32* Wi = smem;               // [32 r'][264]: r'=4s+tig -> per n: {h2(k=16s+2tig), h2(k+8)}
    u32* Xi = smem + WI_WORDS;    // [64 node][72]: h2 per kp, slots interleaved (kp, kp+4 adjacent)

    const int tid  = threadIdx.x;
    const int wid  = tid >> 5;            // 16 warps: 4m x 4n
    const int lane = tid & 31;
    const int gid  = lane >> 2;
    const int tig  = lane & 3;
    const int g    = blockIdx.x;
    const int h    = __ldg(head + g);

    const int m0 = (wid >> 2) * 16;       // 0,16,32,48
    const int n0 = (wid & 3) * 32;        // 0,32,64,96

    // ---- stage W[h] -> Wi (interleaved k-pair rows) ----
    {
        const float4* W4 = (const float4*)(kern + (size_t)h * IN_F * OUT_F);
        #pragma unroll
        for (int it = 0; it < 2; it++) {
            const int idx = tid + it * 512;        // 1024 tasks: 32 r' x 32 col-quads
            const int r   = idx >> 5;              // r' row
            const int c4  = idx & 31;              // float4 col group
            const int k0  = 16 * (r >> 2) + 2 * (r & 3);
            float4 va = W4[(k0)     * 32 + c4];
            float4 vb = W4[(k0 + 1) * 32 + c4];
            float4 vc = W4[(k0 + 8) * 32 + c4];
            float4 vd = W4[(k0 + 9) * 32 + c4];
            uint4 o0, o1;
            o0.x = pack_h2(va.x, vb.x);  o0.y = pack_h2(vc.x, vd.x);
            o0.z = pack_h2(va.y, vb.y);  o0.w = pack_h2(vc.y, vd.y);
            o1.x = pack_h2(va.z, vb.z);  o1.y = pack_h2(vc.z, vd.z);
            o1.z = pack_h2(va.w, vb.w);  o1.w = pack_h2(vc.w, vd.w);
            u32* dst = &Wi[r * WI_STRIDE + c4 * 8];
            *(uint4*)dst       = o0;
            *(uint4*)(dst + 4) = o1;
        }
    }
    // ---- stage X[g] -> Xi (slot-interleaved k-pairs) ----
    {
        const float4* X4 = (const float4*)(x + (size_t)g * NPG * IN_F);
        #pragma unroll
        for (int it = 0; it < 4; it++) {
            const int idx  = tid + it * 512;       // 2048 float4
            const int node = idx >> 5;
            const int c4   = idx & 31;
            float4 v = X4[idx];
            const int kp0   = 2 * c4;
            const int grp   = kp0 >> 3;
            const int slot0 = 2 * (kp0 & 3) + ((kp0 & 7) >> 2);
            u32* dst = &Xi[node * XI_STRIDE + grp * 8];
            dst[slot0]     = pack_h2(v.x, v.y);
            dst[slot0 + 2] = pack_h2(v.z, v.w);
        }
    }
    __syncthreads();

    float acc[4][4];
    #pragma unroll
    for (int j = 0; j < 4; j++)
        #pragma unroll
        for (int r = 0; r < 4; r++)
            acc[j][r] = 0.0f;

    const u32* pA = Xi + (m0 + gid) * XI_STRIDE + 2 * tig;
    const u32* pB = Wi + tig * WI_STRIDE + (n0 + gid) * 2;

    // ---- 8 k16-steps, 2-deep fragment pipeline, all LDS.64 ----
    uint2 aw0[2], aw1[2], bw[2][4];
    {
        aw0[0] = *(const uint2*)(pA);
        aw1[0] = *(const uint2*)(pA + 8 * XI_STRIDE);
        #pragma unroll
        for (int j = 0; j < 4; j++)
            bw[0][j] = *(const uint2*)(pB + 16 * j);
    }

    #pragma unroll
    for (int s = 0; s < 8; s++) {
        const int cur = s & 1, nxt = cur ^ 1;
        if (s < 7) {
            const u32* qa = pA + (s + 1) * 8;
            const u32* qb = pB + (s + 1) * 4 * WI_STRIDE;
            aw0[nxt] = *(const uint2*)(qa);
            aw1[nxt] = *(const uint2*)(qa + 8 * XI_STRIDE);
            #pragma unroll
            for (int j = 0; j < 4; j++)
                bw[nxt][j] = *(const uint2*)(qb + 16 * j);
        }
        const u32 a0 = aw0[cur].x, a2 = aw0[cur].y;
        const u32 a1 = aw1[cur].x, a3 = aw1[cur].y;
        #pragma unroll
        for (int j = 0; j < 4; j++)
            mma_f16(acc[j], a0, a1, a2, a3, bw[cur][j].x, bw[cur][j].y);
    }

    // ---- epilogue: bias + coalesced float2 stores ----
    float bb[4][2];
    #pragma unroll
    for (int j = 0; j < 4; j++) {
        const int col = n0 + 8 * j + 2 * tig;
        bb[j][0] = __ldg(bias + (size_t)h * OUT_F + col);
        bb[j][1] = __ldg(bias + (size_t)h * OUT_F + col + 1);
    }

    const int node0 = g * NPG + m0 + gid;
    #pragma unroll
    for (int j = 0; j < 4; j++) {
        const int col = n0 + 8 * j + 2 * tig;
        float2 v0 = make_float2(acc[j][0] + bb[j][0], acc[j][1] + bb[j][1]);
        float2 v1 = make_float2(acc[j][2] + bb[j][0], acc[j][3] + bb[j][1]);
        *(float2*)&out[(size_t)node0 * OUT_F + col]       = v0;
        *(float2*)&out[(size_t)(node0 + 8) * OUT_F + col] = v1;
    }
}

extern "C" void kernel_launch(void* const* d_in, const int* in_sizes, int n_in,
                              void* d_out, int out_size)
{
    const float* inputs = (const float*)d_in[0];
    const int*   head   = (const int*)d_in[2];
    const float* kern   = (const float*)d_in[3];
    const float* bias   = (const float*)d_in[4];
    float*       out    = (float*)d_out;
    const int n_graphs  = in_sizes[2];   // 256

    static bool attr_set = false;
    if (!attr_set) {
        cudaFuncSetAttribute(mhl_mma_kernel, cudaFuncAttributeMaxDynamicSharedMemorySize, SMEM_BYTES);
        attr_set = true;
    }
    mhl_mma_kernel<<<n_graphs, 512, SMEM_BYTES>>>(inputs, head, kern, bias, out);
}